// round 8
// baseline (speedup 1.0000x reference)
#include <cuda_runtime.h>
#include <cstdint>

#define VSZ 10000   // vocab
#define KD  300     // embedding dim D
#define BB  256     // batch
#define TT  128     // max doc len
#define PP  200     // patterns

#define QP     768                  // packed q columns (700 real)
#define KSEC   320                  // padded K per section
#define NSEC   6
#define NCHS   10                   // chunks (32 k) per section
#define NCHUNK (NSEC * NCHS)        // 60
#define VT     79                   // v tiles of 128
#define QT     3                    // q tiles of 256

// Device scratch (no allocation allowed)
__device__ __align__(16) float    g_table[(size_t)VSZ * QP];            // 30.7 MB
__device__ __align__(16) uint32_t g_Abf[(size_t)VT * NCHUNK * 2048];    // 38.8 MB
__device__ __align__(16) uint32_t g_Bbf[(size_t)QT * NCHUNK * 4096];    // 2.95 MB
__device__ float g_biasp[QP];

__device__ __forceinline__ uint32_t smem_u32(const void* p) {
    uint32_t a;
    asm("{ .reg .u64 t; cvta.to.shared.u64 t, %1; cvt.u32.u64 %0, t; }" : "=r"(a) : "l"(p));
    return a;
}

// packed j (0..699) -> source q = p*5 + l   (end_states = repeat([2,3,4,5],50))
__device__ __forceinline__ int packed_to_src(int j) {
    if (j < 100) return (j >> 1) * 5 + (j & 1);
    if (j < 250) { int r = j - 100; return (50  + r / 3) * 5 + r % 3; }
    if (j < 450) { int r = j - 250; return (100 + r / 4) * 5 + r % 4; }
    { int r = j - 450; return (150 + r / 5) * 5 + r % 5; }
}

// Exact bf16 3-way split via bit masks: x = h + m + l, each exactly bf16.
struct Split3 { uint32_t h, m, l; };   // bf16 bit patterns (16-bit, in low half)
__device__ __forceinline__ Split3 bf16_split3(float x) {
    uint32_t xb = __float_as_uint(x);
    float h = __uint_as_float(xb & 0xFFFF0000u);
    float r1 = x - h;                               // exact
    uint32_t rb = __float_as_uint(r1);
    float m = __uint_as_float(rb & 0xFFFF0000u);
    float l = r1 - m;                               // exact, <=8 sig bits -> bf16-exact
    Split3 s;
    s.h = xb >> 16;
    s.m = rb >> 16;
    s.l = __float_as_uint(l) >> 16;
    return s;
}

// ---------------------------------------------------------------------------
// convA: emb[k][v] -> fragment-permuted bf16 pairs, sections [h,h,h,m,m,l]
// m16n8k16 A-fragment: word(r, kp) at lane=(r%8)*4+(kp%4), reg=(r/8)+2*(kp/4),
// block = mi*2 + ks (mi=16-row group 0..7, ks=k16 half 0..1), word_off = lane*4+reg.
// grid (79, 10), block 256
// ---------------------------------------------------------------------------
__global__ void __launch_bounds__(256) convA_kernel(const float* __restrict__ emb)
{
    __shared__ float xs[32][132];
    const int vt = blockIdx.x, c = blockIdx.y;
    const int tid = threadIdx.x;
    const int v0 = vt * 128, k0 = c * 32;

    for (int e = tid; e < 32 * 128; e += 256) {
        int kk = e >> 7, vm = e & 127;
        int gk = k0 + kk, gv = v0 + vm;
        xs[kk][vm] = (gk < KD && gv < VSZ) ? emb[(size_t)gk * VSZ + gv] : 0.f;
    }
    __syncthreads();

    uint32_t* base = g_Abf + ((size_t)vt * NCHUNK + c) * 2048;
    for (int o = tid; o < 2048; o += 256) {
        int block = o >> 7, w = o & 127;
        int mi = block >> 1, ks = block & 1;
        int lane = w >> 2, reg = w & 3;
        int r  = (reg & 1) * 8 + (lane >> 2);
        int kp = (reg >> 1) * 4 + (lane & 3);
        int vloc = mi * 16 + r;
        int kloc = ks * 16 + kp * 2;
        Split3 s0 = bf16_split3(xs[kloc][vloc]);
        Split3 s1 = bf16_split3(xs[kloc + 1][vloc]);
        uint32_t wh = (s1.h << 16) | s0.h;
        uint32_t wm = (s1.m << 16) | s0.m;
        uint32_t wl = (s1.l << 16) | s0.l;
        base[o]                   = wh;
        base[o + 1 * NCHS * 2048] = wh;
        base[o + 2 * NCHS * 2048] = wh;
        base[o + 3 * NCHS * 2048] = wm;
        base[o + 4 * NCHS * 2048] = wm;
        base[o + 5 * NCHS * 2048] = wl;
    }
}

// ---------------------------------------------------------------------------
// convB: diags[src(j)][k] -> fragment-permuted bf16 pairs, sections [h,m,l,h,m,h]
// m16n8k16 B-fragment (k x n col): word(kp, n) at lane = n_loc*4 + (kp%4), reg = kp/4,
// block = ni*2 + ks, word_off = lane*2 + reg.   grid (3, 10), block 256
// ---------------------------------------------------------------------------
__global__ void __launch_bounds__(256) convB_kernel(const float* __restrict__ diags,
                                                    const float* __restrict__ bias)
{
    const int qt = blockIdx.x, c = blockIdx.y;
    const int tid = threadIdx.x;
    uint32_t* base = g_Bbf + ((size_t)qt * NCHUNK + c) * 4096;

    for (int o = tid; o < 4096; o += 256) {
        int block = o >> 6, w = o & 63;
        int ni = block >> 1, ks = block & 1;
        int lane = w >> 1, reg = w & 1;
        int nloc = lane >> 2;
        int kp = (lane & 3) + reg * 4;
        int j = qt * 256 + ni * 8 + nloc;
        int k = c * 32 + ks * 16 + kp * 2;
        float x0 = 0.f, x1 = 0.f;
        if (j < 700) {
            int src = packed_to_src(j);
            if (k     < KD) x0 = diags[src * KD + k];
            if (k + 1 < KD) x1 = diags[src * KD + k + 1];
        }
        Split3 s0 = bf16_split3(x0);
        Split3 s1 = bf16_split3(x1);
        uint32_t wh = (s1.h << 16) | s0.h;
        uint32_t wm = (s1.m << 16) | s0.m;
        uint32_t wl = (s1.l << 16) | s0.l;
        base[o]                   = wh;
        base[o + 1 * NCHS * 4096] = wm;
        base[o + 2 * NCHS * 4096] = wl;
        base[o + 3 * NCHS * 4096] = wh;
        base[o + 4 * NCHS * 4096] = wm;
        base[o + 5 * NCHS * 4096] = wh;
    }

    if (blockIdx.y == 0) {                        // fold bias packing in
        int j = qt * 256 + tid;
        g_biasp[j] = (j < 700) ? bias[packed_to_src(j)] : 0.f;
    }
}

// ---------------------------------------------------------------------------
// GEMM via mma.sync m16n8k16 bf16 (fp32 accum):
//   g_table[v][j] = sum over 6 exact-split sections + biasp[j]
// CTA tile 128(v) x 256(j), 512 thr / 16 warps (2m x 8n), warp 64x32.
// 3-stage cp.async pipeline over 60 chunks of K=32.
// ---------------------------------------------------------------------------
#define NSTAGE 3
#define STG_A  8192
#define STG_B  16384
#define STG    (STG_A + STG_B)
#define GSMEM  (NSTAGE * STG)     // 73728

__device__ __forceinline__ void mma_bf16(float& d0, float& d1, float& d2, float& d3,
                                         uint32_t a0, uint32_t a1, uint32_t a2, uint32_t a3,
                                         uint32_t b0, uint32_t b1)
{
    asm volatile(
        "mma.sync.aligned.m16n8k16.row.col.f32.bf16.bf16.f32 "
        "{%0,%1,%2,%3}, {%4,%5,%6,%7}, {%8,%9}, {%0,%1,%2,%3};"
        : "+f"(d0), "+f"(d1), "+f"(d2), "+f"(d3)
        : "r"(a0), "r"(a1), "r"(a2), "r"(a3), "r"(b0), "r"(b1));
}

__global__ void __launch_bounds__(512, 2) gemm_kernel()
{
    extern __shared__ __align__(16) char smem[];
    const uint32_t sb = smem_u32(smem);
    const int tid = threadIdx.x;
    const int wid = tid >> 5, lane = tid & 31;
    const int wm = wid & 1, wn = wid >> 1;          // 2 x 8 warp grid
    const int bx = blockIdx.x, by = blockIdx.y;     // q tile (3), v tile (79)

    const uint32_t* Asrc = g_Abf + (size_t)by * NCHUNK * 2048;
    const uint32_t* Bsrc = g_Bbf + (size_t)bx * NCHUNK * 4096;

    auto issue_copy = [&](int chunk) {
        const int s = chunk % NSTAGE;
        uint32_t da = sb + s * STG + tid * 16;
        const uint32_t* ga = Asrc + chunk * 2048 + tid * 4;
        asm volatile("cp.async.cg.shared.global [%0], [%1], 16;" :: "r"(da), "l"(ga));
        uint32_t db = sb + s * STG + STG_A + tid * 16;
        const uint32_t* gb = Bsrc + chunk * 4096 + tid * 4;
#pragma unroll
        for (int i = 0; i < 2; i++)
            asm volatile("cp.async.cg.shared.global [%0], [%1], 16;"
                         :: "r"(db + i * 8192), "l"(gb + i * 2048));
    };

    float d[4][4][4];
#pragma unroll
    for (int mi = 0; mi < 4; mi++)
#pragma unroll
        for (int ni = 0; ni < 4; ni++)
#pragma unroll
            for (int r = 0; r < 4; r++) d[mi][ni][r] = 0.f;

    issue_copy(0);
    asm volatile("cp.async.commit_group;");
    issue_copy(1);
    asm volatile("cp.async.commit_group;");

    for (int c = 0; c < NCHUNK; c++) {
        asm volatile("cp.async.wait_group 1;");
        __syncthreads();
        if (c + 2 < NCHUNK) issue_copy(c + 2);
        asm volatile("cp.async.commit_group;");

        const uint32_t abase = sb + (c % NSTAGE) * STG;
        const uint32_t bbase = abase + STG_A;
#pragma unroll
        for (int ks = 0; ks < 2; ks++) {
            uint32_t a[4][4], b[4][2];
#pragma unroll
            for (int mi = 0; mi < 4; mi++) {
                uint32_t addr = abase + (((wm * 4 + mi) * 2 + ks) << 9) + lane * 16;
                asm volatile("ld.shared.v4.b32 {%0,%1,%2,%3}, [%4];"
                             : "=r"(a[mi][0]), "=r"(a[mi][1]), "=r"(a[mi][2]), "=r"(a[mi][3])
                             : "r"(addr));
            }
#pragma unroll
            for (int ni = 0; ni < 4; ni++) {
                uint32_t addr = bbase + (((wn * 4 + ni) * 2 + ks) << 8) + lane * 8;
                asm volatile("ld.shared.v2.b32 {%0,%1}, [%2];"
                             : "=r"(b[ni][0]), "=r"(b[ni][1]) : "r"(addr));
            }
#pragma unroll
            for (int mi = 0; mi < 4; mi++)
#pragma unroll
                for (int ni = 0; ni < 4; ni++)
                    mma_bf16(d[mi][ni][0], d[mi][ni][1], d[mi][ni][2], d[mi][ni][3],
                             a[mi][0], a[mi][1], a[mi][2], a[mi][3],
                             b[ni][0], b[ni][1]);
        }
        __syncthreads();
    }

    // Epilogue: + packed bias, float2 stores
    const int v0 = by * 128 + wm * 64;
    const int q0 = bx * 256 + wn * 32;
    const int rr = lane >> 2;
    const int qc = (lane & 3) * 2;
#pragma unroll
    for (int mi = 0; mi < 4; mi++) {
#pragma unroll
        for (int half = 0; half < 2; half++) {
            int v = v0 + mi * 16 + rr + half * 8;
            if (v < VSZ) {
                float* row = g_table + (size_t)v * QP;
#pragma unroll
                for (int ni = 0; ni < 4; ni++) {
                    int j = q0 + ni * 8 + qc;
                    float2 val;
                    val.x = d[mi][ni][half * 2 + 0] + g_biasp[j];
                    val.y = d[mi][ni][half * 2 + 1] + g_biasp[j + 1];
                    *reinterpret_cast<float2*>(row + j) = val;
                }
            }
        }
    }
}

// ---------------------------------------------------------------------------
// Scan (verbatim from R7 pass): one block / batch row; 4-slot cp.async
// pipeline, one sync per iteration, packed 768-float rows.
// ---------------------------------------------------------------------------
__global__ void __launch_bounds__(256) scan_kernel(const int* __restrict__ docs,
                                                   const int* __restrict__ doc_lens,
                                                   const int* __restrict__ end_states,
                                                   const float* __restrict__ wild,
                                                   const float* __restrict__ lin_w,
                                                   const float* __restrict__ lin_b,
                                                   float* __restrict__ out)
{
    __shared__ __align__(16) float buf[4][QP];
    __shared__ int   toks[TT];
    __shared__ float wsum[8];
    __shared__ float wsum2[2][8];
    __shared__ float s_mean;

    const int b   = blockIdx.x;
    const int tid = threadIdx.x;
    const int len = doc_lens[b];

    if (tid < TT) toks[tid] = docs[b * TT + tid];

    const bool act = tid < PP;
    float w0 = 0.f, w1 = 0.f, w2 = 0.f, w3 = 0.f, w4 = 0.f;
    int e = 2, base = 0;
    if (act) {
        w0 = wild[tid * 5 + 0];
        w1 = wild[tid * 5 + 1];
        w2 = wild[tid * 5 + 2];
        w3 = wild[tid * 5 + 3];
        w4 = wild[tid * 5 + 4];
        e  = end_states[tid];
        base = (tid < 50)  ? 2 * tid
             : (tid < 100) ? 100 + 3 * (tid - 50)
             : (tid < 150) ? 250 + 4 * (tid - 100)
                           : 450 + 5 * (tid - 150);
    }
    __syncthreads();

    const float NEG = __int_as_float(0xff800000);
    float h1 = NEG, h2 = NEG, h3 = NEG, h4 = NEG, h5 = NEG, sc = NEG;

    const uint32_t sbase = smem_u32(buf);

#pragma unroll
    for (int s = 0; s < 3; s++) {                  // len >= 8 > 3 always
        if (tid < 192) {
            const float* g = g_table + (size_t)toks[s] * QP + tid * 4;
            uint32_t dd = sbase + s * 3072 + tid * 16;
            asm volatile("cp.async.cg.shared.global [%0], [%1], 16;" :: "r"(dd), "l"(g));
        }
        asm volatile("cp.async.commit_group;");
    }

    for (int t = 0; t < len; t++) {
        asm volatile("cp.async.wait_group 2;");
        __syncthreads();
        int tn = t + 3;
        if (tn < len && tid < 192) {
            const float* g = g_table + (size_t)toks[tn] * QP + tid * 4;
            uint32_t dd = sbase + (tn & 3) * 3072 + tid * 16;
            asm volatile("cp.async.cg.shared.global [%0], [%1], 16;" :: "r"(dd), "l"(g));
        }
        asm volatile("cp.async.commit_group;");
        if (act) {
            const float* r = buf[t & 3] + base;
            float t0 = r[0];
            float t1 = r[1];
            float t2 = (e > 2) ? r[2] : NEG;
            float t3 = (e > 3) ? r[3] : NEG;
            float t4 = (e > 4) ? r[4] : NEG;
            float m0 = fmaxf(t0, w0);
            float m1 = fmaxf(t1, w1);
            float m2 = fmaxf(t2, w2);
            float m3 = fmaxf(t3, w3);
            float m4 = fmaxf(t4, w4);
            h5 = h4 + m4;          // uses OLD h4..h1
            h4 = h3 + m3;
            h3 = h2 + m2;
            h2 = h1 + m1;
            h1 = m0;
            float ev = (e == 2) ? h2 : (e == 3) ? h3 : (e == 4) ? h4 : h5;
            sc = fmaxf(sc, ev);
        }
    }

    // LN+binarize collapses to (sc > mean); then 2-wide linear
    const int lane = tid & 31, warp = tid >> 5;

    float x = act ? sc : 0.f;
#pragma unroll
    for (int o = 16; o; o >>= 1) x += __shfl_down_sync(0xffffffffu, x, o);
    if (lane == 0) wsum[warp] = x;
    __syncthreads();
    if (tid == 0) {
        float tot = 0.f;
#pragma unroll
        for (int i = 0; i < 8; i++) tot += wsum[i];
        s_mean = tot / 200.f;
    }
    __syncthreads();
    const float mean = s_mean;

    float c0 = 0.f, c1 = 0.f;
    if (act && sc > mean) {
        c0 = lin_w[tid];
        c1 = lin_w[PP + tid];
    }
#pragma unroll
    for (int o = 16; o; o >>= 1) {
        c0 += __shfl_down_sync(0xffffffffu, c0, o);
        c1 += __shfl_down_sync(0xffffffffu, c1, o);
    }
    if (lane == 0) { wsum2[0][warp] = c0; wsum2[1][warp] = c1; }
    __syncthreads();
    if (tid == 0) {
        float t0 = 0.f, t1 = 0.f;
#pragma unroll
        for (int i = 0; i < 8; i++) { t0 += wsum2[0][i]; t1 += wsum2[1][i]; }
        out[b * 2 + 0] = t0 + lin_b[0];
        out[b * 2 + 1] = t1 + lin_b[1];
    }
}

// ---------------------------------------------------------------------------
extern "C" void kernel_launch(void* const* d_in, const int* in_sizes, int n_in,
                              void* d_out, int out_size)
{
    const int*   docs       = (const int*)  d_in[0];
    const int*   doc_lens   = (const int*)  d_in[1];
    const int*   end_states = (const int*)  d_in[2];
    const float* emb        = (const float*)d_in[3];
    const float* diags      = (const float*)d_in[4];
    const float* bias       = (const float*)d_in[5];
    const float* wild       = (const float*)d_in[6];
    const float* lin_w      = (const float*)d_in[7];
    const float* lin_b      = (const float*)d_in[8];
    float* out = (float*)d_out;

    cudaFuncSetAttribute(gemm_kernel,
                         cudaFuncAttributeMaxDynamicSharedMemorySize, GSMEM);

    convA_kernel<<<dim3(VT, NCHS), 256>>>(emb);
    convB_kernel<<<dim3(QT, NCHS), 256>>>(diags, bias);
    gemm_kernel<<<dim3(QT, VT), 512, GSMEM>>>();
    scan_kernel<<<BB, 256>>>(docs, doc_lens, end_states, wild, lin_w, lin_b, out);
}

// round 9
// speedup vs baseline: 2.5917x; 2.5917x over previous
#include <cuda_runtime.h>
#include <cstdint>

#define VSZ  10000   // vocab
#define KD   300     // embedding dim D
#define BB   256     // batch
#define TT   128     // max doc len
#define PP   200     // patterns

#define QP   768     // packed q columns (700 real, padded)
#define KPAD 304     // K padded to 38*8
#define NKT  38      // k-tiles of 8
#define VTM  79      // max v tiles of 128 (10112 rows)
#define UPAD 10112
#define JT   6       // j tiles of 128
#define NW   313     // bitmap words (10000 bits)

// Device scratch (no allocation allowed)
__device__ __align__(16) float    g_table[(size_t)VSZ * QP];    // 30.7 MB [slot][j]
__device__ __align__(16) float    g_Ac[(size_t)KPAD * UPAD];    // 12.3 MB [k][slot]
__device__ __align__(16) float    g_Bpack[(size_t)KPAD * QP];   // 0.93 MB [k][j]
__device__ float    g_biasp[QP];
__device__ uint32_t g_bits[NW + 7];
__device__ int      g_slot[VSZ];    // token -> compact slot (-1 absent)
__device__ int      g_inv[UPAD];    // slot -> token
__device__ int      g_u;            // number of present tokens

__device__ __forceinline__ uint32_t smem_u32(const void* p) {
    uint32_t a;
    asm("{ .reg .u64 t; cvta.to.shared.u64 t, %1; cvt.u32.u64 %0, t; }" : "=r"(a) : "l"(p));
    return a;
}

// packed j (0..699) -> source q = p*5 + l   (end_states = repeat([2,3,4,5],50))
__device__ __forceinline__ int packed_to_src(int j) {
    if (j < 100) return (j >> 1) * 5 + (j & 1);
    if (j < 250) { int r = j - 100; return (50  + r / 3) * 5 + r % 3; }
    if (j < 450) { int r = j - 250; return (100 + r / 4) * 5 + r % 4; }
    { int r = j - 450; return (150 + r / 5) * 5 + r % 5; }
}

// ---------------------------------------------------------------------------
// 1) zero presence bitmap
__global__ void zero_kernel() {
    int i = threadIdx.x;
    if (i < NW + 7) g_bits[i] = 0u;
}

// 2) mark tokens present within doc_lens
__global__ void __launch_bounds__(128) mark_kernel(const int* __restrict__ docs,
                                                   const int* __restrict__ doc_lens) {
    int b = blockIdx.x, t = threadIdx.x;
    if (t < doc_lens[b]) {
        int v = docs[b * TT + t];
        atomicOr(&g_bits[v >> 5], 1u << (v & 31));
    }
}

// 3) prefix-sum bitmap -> slot/inv/u   (single block, 512 threads)
__global__ void __launch_bounds__(512) slot_kernel() {
    __shared__ uint32_t pre[NW + 1];
    const int tid = threadIdx.x;
    __shared__ uint32_t cnt[NW];
    if (tid < NW) cnt[tid] = __popc(g_bits[tid]);
    __syncthreads();
    if (tid == 0) {
        uint32_t run = 0;
        for (int w = 0; w < NW; w++) { pre[w] = run; run += cnt[w]; }
        pre[NW] = run;
        g_u = (int)run;
    }
    __syncthreads();
    for (int v = tid; v < VSZ; v += 512) {
        uint32_t word = g_bits[v >> 5];
        int bit = v & 31;
        bool present = (word >> bit) & 1u;
        int s = (int)pre[v >> 5] + __popc(word & ((1u << bit) - 1u));
        g_slot[v] = present ? s : -1;
        if (present) g_inv[s] = v;
    }
}

// 4) gather compacted A:  g_Ac[k][i] = emb[k][inv[i]]   grid (40, 304)
__global__ void __launch_bounds__(256) gather_kernel(const float* __restrict__ emb) {
    int i = blockIdx.x * 256 + threadIdx.x;
    int k = blockIdx.y;
    if (i >= UPAD) return;
    int u = g_u;
    float val = 0.f;
    if (i < u && k < KD) val = emb[(size_t)k * VSZ + g_inv[i]];
    g_Ac[(size_t)k * UPAD + i] = val;
}

// 5) pack B + bias
__global__ void __launch_bounds__(256) pack_kernel(const float* __restrict__ diags,
                                                   const float* __restrict__ bias) {
    int idx = blockIdx.x * 256 + threadIdx.x;
    if (idx < KPAD * QP) {
        int k = idx / QP, j = idx % QP;
        g_Bpack[idx] = (k < KD && j < 700) ? diags[packed_to_src(j) * KD + k] : 0.f;
    }
    if (idx < QP)
        g_biasp[idx] = (idx < 700) ? bias[packed_to_src(idx)] : 0.f;
}

// ---------------------------------------------------------------------------
// 6) GEMM (fp32 exact): g_table[i][j] = sum_k g_Ac[k][i]*g_Bpack[k][j] + biasp[j]
// CTA 128(i) x 128(j), 256 thr, 8x8/thread, double-buffered cp.async, k-step 8.
// ---------------------------------------------------------------------------
__global__ void __launch_bounds__(256, 2) gemm_kernel() {
    const int u = g_u;
    const int v0 = blockIdx.y * 128;
    if (v0 >= u) return;                   // early-exit absent tiles

    __shared__ __align__(16) float As[2][8][128];
    __shared__ __align__(16) float Bs[2][8][128];

    const int tid = threadIdx.x;
    const int tv  = tid & 15;
    const int tq  = tid >> 4;
    const int j0  = blockIdx.x * 128;

    const uint32_t sbA = smem_u32(As);
    const uint32_t sbB = smem_u32(Bs);

    const int cl = tid * 4;
    const int ck = cl >> 7;
    const int cv = cl & 127;
    auto issue_copy = [&](int kt, int bf) {
        int gk = kt * 8 + ck;
        const float* ga = g_Ac + (size_t)gk * UPAD + v0 + cv;        // rows >=KD are zeros
        uint32_t da = sbA + (bf * 1024 + ck * 128 + cv) * 4;
        asm volatile("cp.async.cg.shared.global [%0], [%1], 16;" :: "r"(da), "l"(ga));
        const float* gb = g_Bpack + (size_t)gk * QP + j0 + cv;
        uint32_t db = sbB + (bf * 1024 + ck * 128 + cv) * 4;
        asm volatile("cp.async.cg.shared.global [%0], [%1], 16;" :: "r"(db), "l"(gb));
    };

    float acc[8][8];
#pragma unroll
    for (int r = 0; r < 8; r++)
#pragma unroll
        for (int j = 0; j < 8; j++) acc[r][j] = 0.f;

    issue_copy(0, 0);
    asm volatile("cp.async.commit_group;");

    for (int kt = 0; kt < NKT; kt++) {
        if (kt + 1 < NKT) issue_copy(kt + 1, (kt + 1) & 1);
        asm volatile("cp.async.commit_group;");
        asm volatile("cp.async.wait_group 1;");
        __syncthreads();

        const int bf = kt & 1;
#pragma unroll
        for (int kk = 0; kk < 8; kk++) {
            float a[8], b[8];
#pragma unroll
            for (int r = 0; r < 8; r++) a[r] = As[bf][kk][tv * 8 + r];
#pragma unroll
            for (int j = 0; j < 8; j++) b[j] = Bs[bf][kk][tq * 8 + j];
#pragma unroll
            for (int r = 0; r < 8; r++)
#pragma unroll
                for (int j = 0; j < 8; j++)
                    acc[r][j] += a[r] * b[j];
        }
        __syncthreads();
    }

    const int jb = j0 + tq * 8;
    float bv[8];
#pragma unroll
    for (int j = 0; j < 8; j++) bv[j] = g_biasp[jb + j];

#pragma unroll
    for (int r = 0; r < 8; r++) {
        int i = v0 + tv * 8 + r;
        if (i < u) {
            float4* dst = reinterpret_cast<float4*>(&g_table[(size_t)i * QP + jb]);
            dst[0] = make_float4(acc[r][0] + bv[0], acc[r][1] + bv[1],
                                 acc[r][2] + bv[2], acc[r][3] + bv[3]);
            dst[1] = make_float4(acc[r][4] + bv[4], acc[r][5] + bv[5],
                                 acc[r][6] + bv[6], acc[r][7] + bv[7]);
        }
    }
}

// ---------------------------------------------------------------------------
// 7) Scan: one block / batch row; 8-row ring, 2 tokens per barrier.
// ---------------------------------------------------------------------------
__global__ void __launch_bounds__(256) scan_kernel(const int* __restrict__ docs,
                                                   const int* __restrict__ doc_lens,
                                                   const int* __restrict__ end_states,
                                                   const float* __restrict__ wild,
                                                   const float* __restrict__ lin_w,
                                                   const float* __restrict__ lin_b,
                                                   float* __restrict__ out)
{
    __shared__ __align__(16) float buf[8][QP];       // 24.6 KB
    __shared__ int   toks[TT];
    __shared__ float wsum[8];
    __shared__ float wsum2[2][8];
    __shared__ float s_mean;

    const int b   = blockIdx.x;
    const int tid = threadIdx.x;
    const int len = doc_lens[b];

    if (tid < TT) toks[tid] = g_slot[docs[b * TT + tid]];   // rows >= len unused

    const bool act = tid < PP;
    float w0 = 0.f, w1 = 0.f, w2 = 0.f, w3 = 0.f, w4 = 0.f;
    int e = 2, base = 0;
    if (act) {
        w0 = wild[tid * 5 + 0];
        w1 = wild[tid * 5 + 1];
        w2 = wild[tid * 5 + 2];
        w3 = wild[tid * 5 + 3];
        w4 = wild[tid * 5 + 4];
        e  = end_states[tid];
        base = (tid < 50)  ? 2 * tid
             : (tid < 100) ? 100 + 3 * (tid - 50)
             : (tid < 150) ? 250 + 4 * (tid - 100)
                           : 450 + 5 * (tid - 150);
    }
    __syncthreads();

    const float NEG = __int_as_float(0xff800000);
    float h1 = NEG, h2 = NEG, h3 = NEG, h4 = NEG, h5 = NEG, sc = NEG;

    const uint32_t sbase = smem_u32(buf);
    auto fetch_row = [&](int t) {       // row t -> slot t&7 (tid<192 only)
        const float* g = g_table + (size_t)toks[t] * QP + tid * 4;
        uint32_t dd = sbase + (t & 7) * 3072 + tid * 16;
        asm volatile("cp.async.cg.shared.global [%0], [%1], 16;" :: "r"(dd), "l"(g));
    };
    auto step = [&](int t) {
        const float* r = buf[t & 7] + base;
        float t0 = r[0];
        float t1 = r[1];
        float t2 = (e > 2) ? r[2] : NEG;
        float t3 = (e > 3) ? r[3] : NEG;
        float t4 = (e > 4) ? r[4] : NEG;
        float m0 = fmaxf(t0, w0);
        float m1 = fmaxf(t1, w1);
        float m2 = fmaxf(t2, w2);
        float m3 = fmaxf(t3, w3);
        float m4 = fmaxf(t4, w4);
        h5 = h4 + m4;          // uses OLD h4..h1
        h4 = h3 + m3;
        h3 = h2 + m2;
        h2 = h1 + m1;
        h1 = m0;
        float ev = (e == 2) ? h2 : (e == 3) ? h3 : (e == 4) ? h4 : h5;
        sc = fmaxf(sc, ev);
    };

    // prologue: pairs 0..2 (rows 0..5); len >= 8 always
#pragma unroll
    for (int p = 0; p < 3; p++) {
        if (tid < 192) { fetch_row(2 * p); fetch_row(2 * p + 1); }
        asm volatile("cp.async.commit_group;");
    }

    const int npairs = len >> 1;
    for (int p = 0; p < npairs; p++) {
        asm volatile("cp.async.wait_group 2;");
        __syncthreads();
        int r0 = 2 * p + 6;
        if (tid < 192) {
            if (r0     < len) fetch_row(r0);
            if (r0 + 1 < len) fetch_row(r0 + 1);
        }
        asm volatile("cp.async.commit_group;");
        if (act) { step(2 * p); step(2 * p + 1); }
    }
    if (len & 1) {
        asm volatile("cp.async.wait_group 2;");
        __syncthreads();
        if (act) step(len - 1);
    }

    // LN+binarize collapses to (sc > mean); then 2-wide linear
    const int lane = tid & 31, warp = tid >> 5;

    float x = act ? sc : 0.f;
#pragma unroll
    for (int o = 16; o; o >>= 1) x += __shfl_down_sync(0xffffffffu, x, o);
    if (lane == 0) wsum[warp] = x;
    __syncthreads();
    if (tid == 0) {
        float tot = 0.f;
#pragma unroll
        for (int i = 0; i < 8; i++) tot += wsum[i];
        s_mean = tot / 200.f;
    }
    __syncthreads();
    const float mean = s_mean;

    float c0 = 0.f, c1 = 0.f;
    if (act && sc > mean) {
        c0 = lin_w[tid];
        c1 = lin_w[PP + tid];
    }
#pragma unroll
    for (int o = 16; o; o >>= 1) {
        c0 += __shfl_down_sync(0xffffffffu, c0, o);
        c1 += __shfl_down_sync(0xffffffffu, c1, o);
    }
    if (lane == 0) { wsum2[0][warp] = c0; wsum2[1][warp] = c1; }
    __syncthreads();
    if (tid == 0) {
        float t0 = 0.f, t1 = 0.f;
#pragma unroll
        for (int i = 0; i < 8; i++) { t0 += wsum2[0][i]; t1 += wsum2[1][i]; }
        out[b * 2 + 0] = t0 + lin_b[0];
        out[b * 2 + 1] = t1 + lin_b[1];
    }
}

// ---------------------------------------------------------------------------
extern "C" void kernel_launch(void* const* d_in, const int* in_sizes, int n_in,
                              void* d_out, int out_size)
{
    const int*   docs       = (const int*)  d_in[0];
    const int*   doc_lens   = (const int*)  d_in[1];
    const int*   end_states = (const int*)  d_in[2];
    const float* emb        = (const float*)d_in[3];
    const float* diags      = (const float*)d_in[4];
    const float* bias       = (const float*)d_in[5];
    const float* wild       = (const float*)d_in[6];
    const float* lin_w      = (const float*)d_in[7];
    const float* lin_b      = (const float*)d_in[8];
    float* out = (float*)d_out;

    zero_kernel<<<1, 320>>>();
    mark_kernel<<<BB, 128>>>(docs, doc_lens);
    slot_kernel<<<1, 512>>>();
    gather_kernel<<<dim3((UPAD + 255) / 256, KPAD), 256>>>(emb);
    pack_kernel<<<(KPAD * QP + 255) / 256, 256>>>(diags, bias);
    gemm_kernel<<<dim3(JT, VTM), 256>>>();
    scan_kernel<<<BB, 256>>>(docs, doc_lens, end_states, wild, lin_w, lin_b, out);
}

// round 10
// speedup vs baseline: 2.9893x; 1.1534x over previous
#include <cuda_runtime.h>
#include <cstdint>

#define VSZ  10000   // vocab
#define KD   300     // embedding dim D
#define BB   256     // batch
#define TT   128     // max doc len
#define PP   200     // patterns

#define QP   704     // packed q columns (700 real, padded to 11*64)
#define KPAD 304     // K padded to 38*8
#define NKT  38      // k-tiles of 8
#define UPAD 10240   // 40 v-tiles of 256
#define VTM  40
#define JT   11      // j tiles of 64
#define NW   313     // bitmap words (10000 bits)

// Device scratch (no allocation allowed)
__device__ __align__(16) float    g_table[(size_t)UPAD * QP];   // 28.8 MB [slot][j]
__device__ __align__(16) float    g_Bpack[(size_t)KPAD * QP];   // 0.86 MB [k][j]
__device__ float    g_biasp[QP];
__device__ uint32_t g_bits[NW + 7];
__device__ int      g_slot[VSZ];    // token -> compact slot
__device__ int      g_inv[UPAD];    // slot -> token (0-filled tail)
__device__ int      g_u;            // number of present tokens

__device__ __forceinline__ uint32_t smem_u32(const void* p) {
    uint32_t a;
    asm("{ .reg .u64 t; cvta.to.shared.u64 t, %1; cvt.u32.u64 %0, t; }" : "=r"(a) : "l"(p));
    return a;
}

// packed j (0..699) -> source q = p*5 + l   (end_states = repeat([2,3,4,5],50))
__device__ __forceinline__ int packed_to_src(int j) {
    if (j < 100) return (j >> 1) * 5 + (j & 1);
    if (j < 250) { int r = j - 100; return (50  + r / 3) * 5 + r % 3; }
    if (j < 450) { int r = j - 250; return (100 + r / 4) * 5 + r % 4; }
    { int r = j - 450; return (150 + r / 5) * 5 + r % 5; }
}

// ---------------------------------------------------------------------------
// 1) pack B + bias, and zero the presence bitmap (independent of mark/slot)
__global__ void __launch_bounds__(256) pack_kernel(const float* __restrict__ diags,
                                                   const float* __restrict__ bias) {
    int idx = blockIdx.x * 256 + threadIdx.x;
    if (idx < KPAD * QP) {
        int k = idx / QP, j = idx % QP;
        g_Bpack[idx] = (k < KD && j < 700) ? diags[packed_to_src(j) * KD + k] : 0.f;
    }
    if (idx < QP)
        g_biasp[idx] = (idx < 700) ? bias[packed_to_src(idx)] : 0.f;
    if (idx < NW + 7)
        g_bits[idx] = 0u;
}

// 2) mark tokens present within doc_lens
__global__ void __launch_bounds__(128) mark_kernel(const int* __restrict__ docs,
                                                   const int* __restrict__ doc_lens) {
    int b = blockIdx.x, t = threadIdx.x;
    if (t < doc_lens[b]) {
        int v = docs[b * TT + t];
        atomicOr(&g_bits[v >> 5], 1u << (v & 31));
    }
}

// 3) parallel prefix over bitmap -> slot/inv/u   (single block, 512 threads)
__global__ void __launch_bounds__(512) slot_kernel() {
    __shared__ int pre[NW];        // exclusive word prefix
    __shared__ int wtot[16];
    __shared__ int s_u;
    const int tid = threadIdx.x, lane = tid & 31, w = tid >> 5;

    int val = (tid < NW) ? __popc(g_bits[tid]) : 0;
    int incl = val;
#pragma unroll
    for (int o = 1; o < 32; o <<= 1) {
        int y = __shfl_up_sync(0xffffffffu, incl, o);
        if (lane >= o) incl += y;
    }
    if (lane == 31) wtot[w] = incl;
    __syncthreads();
    if (w == 0) {
        int t = (lane < 16) ? wtot[lane] : 0;
#pragma unroll
        for (int o = 1; o < 16; o <<= 1) {
            int y = __shfl_up_sync(0xffffffffu, t, o);
            if (lane >= o) t += y;
        }
        if (lane < 16) wtot[lane] = t;
        if (lane == 15) s_u = t;
    }
    __syncthreads();
    int off = (w > 0) ? wtot[w - 1] : 0;
    if (tid < NW) pre[tid] = incl - val + off;
    if (tid == 0) g_u = s_u;
    __syncthreads();

    const int u = s_u;
    for (int v = tid; v < VSZ; v += 512) {
        uint32_t word = g_bits[v >> 5];
        int bit = v & 31;
        bool present = (word >> bit) & 1u;
        int s = pre[v >> 5] + __popc(word & ((1u << bit) - 1u));
        g_slot[v] = present ? s : -1;
        if (present) g_inv[s] = v;
    }
    for (int s = u + tid; s < UPAD; s += 512) g_inv[s] = 0;
}

// ---------------------------------------------------------------------------
// 4) GEMM (fp32 exact, indirect A): table[i][j] = sum_k emb[k][inv[i]]*Bpack[k][j]+bias
// CTA 256(i) x 64(j), 256 thr, 8x8/thread. Reg-buffered LDG A, cp.async B,
// ONE __syncthreads per k-tile.
// ---------------------------------------------------------------------------
__global__ void __launch_bounds__(256, 2) gemm_kernel(const float* __restrict__ emb) {
    const int u = g_u;
    const int v0 = blockIdx.y * 256;
    if (v0 >= u) return;

    __shared__ __align__(16) float As[2][8][256];   // 16 KB
    __shared__ __align__(16) float Bs[2][8][64];    //  4 KB

    const int tid = threadIdx.x;
    const int ln  = tid & 31;
    const int ck  = tid >> 5;       // k-row for A staging (0..7)
    const int tv  = tid & 31;       // compute: rows tv*8..+7
    const int tq  = tid >> 5;       // compute: cols tq*8..+7
    const int j0  = blockIdx.x * 64;

    // slot -> token, held in regs for the whole CTA lifetime
    int iv[8];
#pragma unroll
    for (int s = 0; s < 8; s++) iv[s] = g_inv[v0 + ln + s * 32];

    const uint32_t sbB = smem_u32(Bs);
    auto issue_B = [&](int kt, int bf) {            // tid<128: 16B each
        if (tid < 128) {
            const float* gb = g_Bpack + (size_t)(kt * 8 + (tid >> 4)) * QP
                              + j0 + (tid & 15) * 4;
            uint32_t db = sbB + (bf * 2048 + (tid >> 4) * 256 + (tid & 15) * 16);
            asm volatile("cp.async.cg.shared.global [%0], [%1], 16;" :: "r"(db), "l"(gb));
        }
    };
    auto ldg_A = [&](int kt, float* av) {
        int gk = kt * 8 + ck;
        const float* rowp = emb + (size_t)gk * VSZ;
        bool ok = gk < KD;
#pragma unroll
        for (int s = 0; s < 8; s++) av[s] = ok ? __ldg(rowp + iv[s]) : 0.f;
    };
    auto sts_A = [&](int bf, const float* av) {
#pragma unroll
        for (int s = 0; s < 8; s++) As[bf][ck][ln + s * 32] = av[s];
    };

    float acc[8][8];
#pragma unroll
    for (int r = 0; r < 8; r++)
#pragma unroll
        for (int j = 0; j < 8; j++) acc[r][j] = 0.f;

    {   // prologue: stage k-tile 0
        float av[8];
        ldg_A(0, av);
        issue_B(0, 0);
        asm volatile("cp.async.commit_group;");
        sts_A(0, av);
        asm volatile("cp.async.wait_group 0;");
        __syncthreads();
    }

    for (int kt = 0; kt < NKT; kt++) {
        const bool more = (kt + 1 < NKT);
        float av[8];
        if (more) {
            ldg_A(kt + 1, av);
            issue_B(kt + 1, (kt + 1) & 1);
        }
        asm volatile("cp.async.commit_group;");

        const int c = kt & 1;
#pragma unroll
        for (int kk = 0; kk < 8; kk++) {
            const float4* ap = reinterpret_cast<const float4*>(&As[c][kk][tv * 8]);
            float4 a0 = ap[0], a1 = ap[1];
            const float4* bp = reinterpret_cast<const float4*>(&Bs[c][kk][tq * 8]);
            float4 b0 = bp[0], b1 = bp[1];
            float a[8] = {a0.x, a0.y, a0.z, a0.w, a1.x, a1.y, a1.z, a1.w};
            float b[8] = {b0.x, b0.y, b0.z, b0.w, b1.x, b1.y, b1.z, b1.w};
#pragma unroll
            for (int r = 0; r < 8; r++)
#pragma unroll
                for (int j = 0; j < 8; j++)
                    acc[r][j] += a[r] * b[j];
        }

        if (more) sts_A((kt + 1) & 1, av);
        asm volatile("cp.async.wait_group 0;");
        __syncthreads();
    }

    // Epilogue: + packed bias, float4 stores
    float bv[8];
#pragma unroll
    for (int j = 0; j < 8; j++) bv[j] = g_biasp[j0 + tq * 8 + j];

#pragma unroll
    for (int r = 0; r < 8; r++) {
        int i = v0 + tv * 8 + r;
        if (i < u) {
            float4* dst = reinterpret_cast<float4*>(&g_table[(size_t)i * QP + j0 + tq * 8]);
            dst[0] = make_float4(acc[r][0] + bv[0], acc[r][1] + bv[1],
                                 acc[r][2] + bv[2], acc[r][3] + bv[3]);
            dst[1] = make_float4(acc[r][4] + bv[4], acc[r][5] + bv[5],
                                 acc[r][6] + bv[6], acc[r][7] + bv[7]);
        }
    }
}

// ---------------------------------------------------------------------------
// 5) Scan: one block / batch row; 8-row ring, 2 tokens per barrier.
// ---------------------------------------------------------------------------
__global__ void __launch_bounds__(256) scan_kernel(const int* __restrict__ docs,
                                                   const int* __restrict__ doc_lens,
                                                   const int* __restrict__ end_states,
                                                   const float* __restrict__ wild,
                                                   const float* __restrict__ lin_w,
                                                   const float* __restrict__ lin_b,
                                                   float* __restrict__ out)
{
    __shared__ __align__(16) float buf[8][QP];       // 22.5 KB
    __shared__ int   toks[TT];
    __shared__ float wsum[8];
    __shared__ float wsum2[2][8];
    __shared__ float s_mean;

    const int b   = blockIdx.x;
    const int tid = threadIdx.x;
    const int len = doc_lens[b];

    if (tid < TT) toks[tid] = g_slot[docs[b * TT + tid]];   // valid for t < len

    const bool act = tid < PP;
    float w0 = 0.f, w1 = 0.f, w2 = 0.f, w3 = 0.f, w4 = 0.f;
    int e = 2, base = 0;
    if (act) {
        w0 = wild[tid * 5 + 0];
        w1 = wild[tid * 5 + 1];
        w2 = wild[tid * 5 + 2];
        w3 = wild[tid * 5 + 3];
        w4 = wild[tid * 5 + 4];
        e  = end_states[tid];
        base = (tid < 50)  ? 2 * tid
             : (tid < 100) ? 100 + 3 * (tid - 50)
             : (tid < 150) ? 250 + 4 * (tid - 100)
                           : 450 + 5 * (tid - 150);
    }
    __syncthreads();

    const float NEG = __int_as_float(0xff800000);
    float h1 = NEG, h2 = NEG, h3 = NEG, h4 = NEG, h5 = NEG, sc = NEG;

    const uint32_t sbase = smem_u32(buf);
    auto fetch_row = [&](int t) {       // tid < 176 only
        const float* g = g_table + (size_t)toks[t] * QP + tid * 4;
        uint32_t dd = sbase + (t & 7) * (QP * 4) + tid * 16;
        asm volatile("cp.async.cg.shared.global [%0], [%1], 16;" :: "r"(dd), "l"(g));
    };
    auto step = [&](int t) {
        const float* r = buf[t & 7] + base;
        float t0 = r[0];
        float t1 = r[1];
        float t2 = (e > 2) ? r[2] : NEG;
        float t3 = (e > 3) ? r[3] : NEG;
        float t4 = (e > 4) ? r[4] : NEG;
        float m0 = fmaxf(t0, w0);
        float m1 = fmaxf(t1, w1);
        float m2 = fmaxf(t2, w2);
        float m3 = fmaxf(t3, w3);
        float m4 = fmaxf(t4, w4);
        h5 = h4 + m4;          // uses OLD h4..h1
        h4 = h3 + m3;
        h3 = h2 + m2;
        h2 = h1 + m1;
        h1 = m0;
        float ev = (e == 2) ? h2 : (e == 3) ? h3 : (e == 4) ? h4 : h5;
        sc = fmaxf(sc, ev);
    };

    // prologue: pairs 0..2 (rows 0..5); len >= 8 always
#pragma unroll
    for (int p = 0; p < 3; p++) {
        if (tid < 176) { fetch_row(2 * p); fetch_row(2 * p + 1); }
        asm volatile("cp.async.commit_group;");
    }

    const int npairs = len >> 1;
    for (int p = 0; p < npairs; p++) {
        asm volatile("cp.async.wait_group 2;");
        __syncthreads();
        int r0 = 2 * p + 6;
        if (tid < 176) {
            if (r0     < len) fetch_row(r0);
            if (r0 + 1 < len) fetch_row(r0 + 1);
        }
        asm volatile("cp.async.commit_group;");
        if (act) { step(2 * p); step(2 * p + 1); }
    }
    if (len & 1) {
        asm volatile("cp.async.wait_group 2;");
        __syncthreads();
        if (act) step(len - 1);
    }

    // LN+binarize collapses to (sc > mean); then 2-wide linear
    const int lane = tid & 31, warp = tid >> 5;

    float x = act ? sc : 0.f;
#pragma unroll
    for (int o = 16; o; o >>= 1) x += __shfl_down_sync(0xffffffffu, x, o);
    if (lane == 0) wsum[warp] = x;
    __syncthreads();
    if (tid == 0) {
        float tot = 0.f;
#pragma unroll
        for (int i = 0; i < 8; i++) tot += wsum[i];
        s_mean = tot / 200.f;
    }
    __syncthreads();
    const float mean = s_mean;

    float c0 = 0.f, c1 = 0.f;
    if (act && sc > mean) {
        c0 = lin_w[tid];
        c1 = lin_w[PP + tid];
    }
#pragma unroll
    for (int o = 16; o; o >>= 1) {
        c0 += __shfl_down_sync(0xffffffffu, c0, o);
        c1 += __shfl_down_sync(0xffffffffu, c1, o);
    }
    if (lane == 0) { wsum2[0][warp] = c0; wsum2[1][warp] = c1; }
    __syncthreads();
    if (tid == 0) {
        float t0 = 0.f, t1 = 0.f;
#pragma unroll
        for (int i = 0; i < 8; i++) { t0 += wsum2[0][i]; t1 += wsum2[1][i]; }
        out[b * 2 + 0] = t0 + lin_b[0];
        out[b * 2 + 1] = t1 + lin_b[1];
    }
}

// ---------------------------------------------------------------------------
extern "C" void kernel_launch(void* const* d_in, const int* in_sizes, int n_in,
                              void* d_out, int out_size)
{
    const int*   docs       = (const int*)  d_in[0];
    const int*   doc_lens   = (const int*)  d_in[1];
    const int*   end_states = (const int*)  d_in[2];
    const float* emb        = (const float*)d_in[3];
    const float* diags      = (const float*)d_in[4];
    const float* bias       = (const float*)d_in[5];
    const float* wild       = (const float*)d_in[6];
    const float* lin_w      = (const float*)d_in[7];
    const float* lin_b      = (const float*)d_in[8];
    float* out = (float*)d_out;

    pack_kernel<<<(KPAD * QP + 255) / 256, 256>>>(diags, bias);
    mark_kernel<<<BB, 128>>>(docs, doc_lens);
    slot_kernel<<<1, 512>>>();
    gemm_kernel<<<dim3(JT, VTM), 256>>>(emb);
    scan_kernel<<<BB, 256>>>(docs, doc_lens, end_states, wild, lin_w, lin_b, out);
}

// round 11
// speedup vs baseline: 3.1150x; 1.0420x over previous
#include <cuda_runtime.h>
#include <cstdint>

#define VSZ  10000   // vocab
#define KD   300     // embedding dim D
#define BB   256     // batch
#define TT   128     // max doc len
#define PP   200     // patterns

#define QP   704     // packed q columns (700 real, padded to 11*64)
#define KPAD 304     // K padded to 38*8
#define NKT  38      // k-tiles of 8
#define UPAD 10112   // 79 v-tiles of 128
#define VTM  79
#define JT   11      // j tiles of 64
#define NW   313     // bitmap words (10000 bits)

// Device scratch (no allocation allowed)
__device__ __align__(16) float    g_table[(size_t)UPAD * QP];   // 28.5 MB [slot][j]
__device__ __align__(16) float    g_Bpack[(size_t)KPAD * QP];   // 0.86 MB [k][j]
__device__ float    g_biasp[QP];
__device__ uint32_t g_bits[NW + 7];
__device__ int      g_slot[VSZ];    // token -> compact slot
__device__ int      g_inv[UPAD];    // slot -> token (0-filled tail)
__device__ int      g_u;            // number of present tokens

__device__ __forceinline__ uint32_t smem_u32(const void* p) {
    uint32_t a;
    asm("{ .reg .u64 t; cvta.to.shared.u64 t, %1; cvt.u32.u64 %0, t; }" : "=r"(a) : "l"(p));
    return a;
}

// packed j (0..699) -> source q = p*5 + l   (end_states = repeat([2,3,4,5],50))
__device__ __forceinline__ int packed_to_src(int j) {
    if (j < 100) return (j >> 1) * 5 + (j & 1);
    if (j < 250) { int r = j - 100; return (50  + r / 3) * 5 + r % 3; }
    if (j < 450) { int r = j - 250; return (100 + r / 4) * 5 + r % 4; }
    { int r = j - 450; return (150 + r / 5) * 5 + r % 5; }
}

// ---------------------------------------------------------------------------
// 1) pack B + bias, and zero the presence bitmap
__global__ void __launch_bounds__(256) pack_kernel(const float* __restrict__ diags,
                                                   const float* __restrict__ bias) {
    int idx = blockIdx.x * 256 + threadIdx.x;
    if (idx < KPAD * QP) {
        int k = idx / QP, j = idx % QP;
        g_Bpack[idx] = (k < KD && j < 700) ? diags[packed_to_src(j) * KD + k] : 0.f;
    }
    if (idx < QP)
        g_biasp[idx] = (idx < 700) ? bias[packed_to_src(idx)] : 0.f;
    if (idx < NW + 7)
        g_bits[idx] = 0u;
}

// 2) mark tokens present within doc_lens
__global__ void __launch_bounds__(128) mark_kernel(const int* __restrict__ docs,
                                                   const int* __restrict__ doc_lens) {
    int b = blockIdx.x, t = threadIdx.x;
    if (t < doc_lens[b]) {
        int v = docs[b * TT + t];
        atomicOr(&g_bits[v >> 5], 1u << (v & 31));
    }
}

// 3) parallel prefix over bitmap -> slot/inv/u   (single block, 512 threads)
__global__ void __launch_bounds__(512) slot_kernel() {
    __shared__ int pre[NW];        // exclusive word prefix
    __shared__ int wtot[16];
    __shared__ int s_u;
    const int tid = threadIdx.x, lane = tid & 31, w = tid >> 5;

    int val = (tid < NW) ? __popc(g_bits[tid]) : 0;
    int incl = val;
#pragma unroll
    for (int o = 1; o < 32; o <<= 1) {
        int y = __shfl_up_sync(0xffffffffu, incl, o);
        if (lane >= o) incl += y;
    }
    if (lane == 31) wtot[w] = incl;
    __syncthreads();
    if (w == 0) {
        int t = (lane < 16) ? wtot[lane] : 0;
#pragma unroll
        for (int o = 1; o < 16; o <<= 1) {
            int y = __shfl_up_sync(0xffffffffu, t, o);
            if (lane >= o) t += y;
        }
        if (lane < 16) wtot[lane] = t;
        if (lane == 15) s_u = t;
    }
    __syncthreads();
    int off = (w > 0) ? wtot[w - 1] : 0;
    if (tid < NW) pre[tid] = incl - val + off;
    if (tid == 0) g_u = s_u;
    __syncthreads();

    const int u = s_u;
    for (int v = tid; v < VSZ; v += 512) {
        uint32_t word = g_bits[v >> 5];
        int bit = v & 31;
        bool present = (word >> bit) & 1u;
        int s = pre[v >> 5] + __popc(word & ((1u << bit) - 1u));
        g_slot[v] = present ? s : -1;
        if (present) g_inv[s] = v;
    }
    for (int s = u + tid; s < UPAD; s += 512) g_inv[s] = 0;
}

// ---------------------------------------------------------------------------
// 4) GEMM (fp32 exact, indirect A): table[i][j] = sum_k emb[k][inv[i]]*Bpack[k][j]+bias
// CTA 128(i) x 64(j), 128 thr, 8x8/thread, 4 CTAs/SM.
// Reg-buffered LDG A, cp.async B, one __syncthreads per k-tile.
// ---------------------------------------------------------------------------
__global__ void __launch_bounds__(128, 4) gemm_kernel(const float* __restrict__ emb) {
    const int u = g_u;
    const int v0 = blockIdx.y * 128;
    if (v0 >= u) return;

    __shared__ __align__(16) float As[2][8][128];   // 8 KB
    __shared__ __align__(16) float Bs[2][8][64];    // 4 KB

    const int tid = threadIdx.x;
    const int ln  = tid & 15;       // A staging: v sub-lane
    const int ck  = tid >> 4;       // A staging: k row (0..7)
    const int tv  = tid & 15;       // compute: rows tv*8..+7
    const int tq  = tid >> 4;       // compute: cols tq*8..+7
    const int j0  = blockIdx.x * 64;

    // slot -> token, held in regs for the whole CTA lifetime
    int iv[8];
#pragma unroll
    for (int s = 0; s < 8; s++) iv[s] = g_inv[v0 + ln + s * 16];

    const uint32_t sbB = smem_u32(Bs);
    auto issue_B = [&](int kt, int bf) {            // all 128 thr: 16B each
        const float* gb = g_Bpack + (size_t)(kt * 8 + ck) * QP + j0 + ln * 4;
        uint32_t db = sbB + (bf * 2048 + ck * 256 + ln * 16);
        asm volatile("cp.async.cg.shared.global [%0], [%1], 16;" :: "r"(db), "l"(gb));
    };
    auto ldg_A = [&](int kt, float* av) {
        int gk = kt * 8 + ck;
        const float* rowp = emb + (size_t)gk * VSZ;
        bool ok = gk < KD;
#pragma unroll
        for (int s = 0; s < 8; s++) av[s] = ok ? __ldg(rowp + iv[s]) : 0.f;
    };
    auto sts_A = [&](int bf, const float* av) {
#pragma unroll
        for (int s = 0; s < 8; s++) As[bf][ck][ln + s * 16] = av[s];
    };

    float acc[8][8];
#pragma unroll
    for (int r = 0; r < 8; r++)
#pragma unroll
        for (int j = 0; j < 8; j++) acc[r][j] = 0.f;

    {   // prologue: stage k-tile 0
        float av[8];
        ldg_A(0, av);
        issue_B(0, 0);
        asm volatile("cp.async.commit_group;");
        sts_A(0, av);
        asm volatile("cp.async.wait_group 0;");
        __syncthreads();
    }

    for (int kt = 0; kt < NKT; kt++) {
        const bool more = (kt + 1 < NKT);
        float av[8];
        if (more) {
            ldg_A(kt + 1, av);
            issue_B(kt + 1, (kt + 1) & 1);
        }
        asm volatile("cp.async.commit_group;");

        const int c = kt & 1;
#pragma unroll
        for (int kk = 0; kk < 8; kk++) {
            const float4* ap = reinterpret_cast<const float4*>(&As[c][kk][tv * 8]);
            float4 a0 = ap[0], a1 = ap[1];
            const float4* bp = reinterpret_cast<const float4*>(&Bs[c][kk][tq * 8]);
            float4 b0 = bp[0], b1 = bp[1];
            float a[8] = {a0.x, a0.y, a0.z, a0.w, a1.x, a1.y, a1.z, a1.w};
            float b[8] = {b0.x, b0.y, b0.z, b0.w, b1.x, b1.y, b1.z, b1.w};
#pragma unroll
            for (int r = 0; r < 8; r++)
#pragma unroll
                for (int j = 0; j < 8; j++)
                    acc[r][j] += a[r] * b[j];
        }

        if (more) sts_A((kt + 1) & 1, av);
        asm volatile("cp.async.wait_group 0;");
        __syncthreads();
    }

    // Epilogue: + packed bias, float4 stores
    float bv[8];
#pragma unroll
    for (int j = 0; j < 8; j++) bv[j] = g_biasp[j0 + tq * 8 + j];

#pragma unroll
    for (int r = 0; r < 8; r++) {
        int i = v0 + tv * 8 + r;
        if (i < u) {
            float4* dst = reinterpret_cast<float4*>(&g_table[(size_t)i * QP + j0 + tq * 8]);
            dst[0] = make_float4(acc[r][0] + bv[0], acc[r][1] + bv[1],
                                 acc[r][2] + bv[2], acc[r][3] + bv[3]);
            dst[1] = make_float4(acc[r][4] + bv[4], acc[r][5] + bv[5],
                                 acc[r][6] + bv[6], acc[r][7] + bv[7]);
        }
    }
}

// ---------------------------------------------------------------------------
// 5) Scan: one block / batch row; 8-row ring, 2 tokens per barrier.
// ---------------------------------------------------------------------------
__global__ void __launch_bounds__(256) scan_kernel(const int* __restrict__ docs,
                                                   const int* __restrict__ doc_lens,
                                                   const int* __restrict__ end_states,
                                                   const float* __restrict__ wild,
                                                   const float* __restrict__ lin_w,
                                                   const float* __restrict__ lin_b,
                                                   float* __restrict__ out)
{
    __shared__ __align__(16) float buf[8][QP];       // 22 KB
    __shared__ int   toks[TT];
    __shared__ float wsum[8];
    __shared__ float wsum2[2][8];
    __shared__ float s_mean;

    const int b   = blockIdx.x;
    const int tid = threadIdx.x;
    const int len = doc_lens[b];

    if (tid < TT) toks[tid] = g_slot[docs[b * TT + tid]];   // valid for t < len

    const bool act = tid < PP;
    float w0 = 0.f, w1 = 0.f, w2 = 0.f, w3 = 0.f, w4 = 0.f;
    int e = 2, base = 0;
    if (act) {
        w0 = wild[tid * 5 + 0];
        w1 = wild[tid * 5 + 1];
        w2 = wild[tid * 5 + 2];
        w3 = wild[tid * 5 + 3];
        w4 = wild[tid * 5 + 4];
        e  = end_states[tid];
        base = (tid < 50)  ? 2 * tid
             : (tid < 100) ? 100 + 3 * (tid - 50)
             : (tid < 150) ? 250 + 4 * (tid - 100)
                           : 450 + 5 * (tid - 150);
    }
    __syncthreads();

    const float NEG = __int_as_float(0xff800000);
    float h1 = NEG, h2 = NEG, h3 = NEG, h4 = NEG, h5 = NEG, sc = NEG;

    const uint32_t sbase = smem_u32(buf);
    auto fetch_row = [&](int t) {       // tid < 176 only
        const float* g = g_table + (size_t)toks[t] * QP + tid * 4;
        uint32_t dd = sbase + (t & 7) * (QP * 4) + tid * 16;
        asm volatile("cp.async.cg.shared.global [%0], [%1], 16;" :: "r"(dd), "l"(g));
    };
    auto step = [&](int t) {
        const float* r = buf[t & 7] + base;
        float t0 = r[0];
        float t1 = r[1];
        float t2 = (e > 2) ? r[2] : NEG;
        float t3 = (e > 3) ? r[3] : NEG;
        float t4 = (e > 4) ? r[4] : NEG;
        float m0 = fmaxf(t0, w0);
        float m1 = fmaxf(t1, w1);
        float m2 = fmaxf(t2, w2);
        float m3 = fmaxf(t3, w3);
        float m4 = fmaxf(t4, w4);
        h5 = h4 + m4;          // uses OLD h4..h1
        h4 = h3 + m3;
        h3 = h2 + m2;
        h2 = h1 + m1;
        h1 = m0;
        float ev = (e == 2) ? h2 : (e == 3) ? h3 : (e == 4) ? h4 : h5;
        sc = fmaxf(sc, ev);
    };

    // prologue: pairs 0..2 (rows 0..5); len >= 8 always
#pragma unroll
    for (int p = 0; p < 3; p++) {
        if (tid < 176) { fetch_row(2 * p); fetch_row(2 * p + 1); }
        asm volatile("cp.async.commit_group;");
    }

    const int npairs = len >> 1;
    for (int p = 0; p < npairs; p++) {
        asm volatile("cp.async.wait_group 2;");
        __syncthreads();
        int r0 = 2 * p + 6;
        if (tid < 176) {
            if (r0     < len) fetch_row(r0);
            if (r0 + 1 < len) fetch_row(r0 + 1);
        }
        asm volatile("cp.async.commit_group;");
        if (act) { step(2 * p); step(2 * p + 1); }
    }
    if (len & 1) {
        asm volatile("cp.async.wait_group 2;");
        __syncthreads();
        if (act) step(len - 1);
    }

    // LN+binarize collapses to (sc > mean); then 2-wide linear
    const int lane = tid & 31, warp = tid >> 5;

    float x = act ? sc : 0.f;
#pragma unroll
    for (int o = 16; o; o >>= 1) x += __shfl_down_sync(0xffffffffu, x, o);
    if (lane == 0) wsum[warp] = x;
    __syncthreads();
    if (tid == 0) {
        float tot = 0.f;
#pragma unroll
        for (int i = 0; i < 8; i++) tot += wsum[i];
        s_mean = tot / 200.f;
    }
    __syncthreads();
    const float mean = s_mean;

    float c0 = 0.f, c1 = 0.f;
    if (act && sc > mean) {
        c0 = lin_w[tid];
        c1 = lin_w[PP + tid];
    }
#pragma unroll
    for (int o = 16; o; o >>= 1) {
        c0 += __shfl_down_sync(0xffffffffu, c0, o);
        c1 += __shfl_down_sync(0xffffffffu, c1, o);
    }
    if (lane == 0) { wsum2[0][warp] = c0; wsum2[1][warp] = c1; }
    __syncthreads();
    if (tid == 0) {
        float t0 = 0.f, t1 = 0.f;
#pragma unroll
        for (int i = 0; i < 8; i++) { t0 += wsum2[0][i]; t1 += wsum2[1][i]; }
        out[b * 2 + 0] = t0 + lin_b[0];
        out[b * 2 + 1] = t1 + lin_b[1];
    }
}

// ---------------------------------------------------------------------------
extern "C" void kernel_launch(void* const* d_in, const int* in_sizes, int n_in,
                              void* d_out, int out_size)
{
    const int*   docs       = (const int*)  d_in[0];
    const int*   doc_lens   = (const int*)  d_in[1];
    const int*   end_states = (const int*)  d_in[2];
    const float* emb        = (const float*)d_in[3];
    const float* diags      = (const float*)d_in[4];
    const float* bias       = (const float*)d_in[5];
    const float* wild       = (const float*)d_in[6];
    const float* lin_w      = (const float*)d_in[7];
    const float* lin_b      = (const float*)d_in[8];
    float* out = (float*)d_out;

    pack_kernel<<<(KPAD * QP + 255) / 256, 256>>>(diags, bias);
    mark_kernel<<<BB, 128>>>(docs, doc_lens);
    slot_kernel<<<1, 512>>>();
    gemm_kernel<<<dim3(JT, VTM), 128>>>(emb);
    scan_kernel<<<BB, 256>>>(docs, doc_lens, end_states, wild, lin_w, lin_b, out);
}